// round 4
// baseline (speedup 1.0000x reference)
#include <cuda_runtime.h>
#include <math.h>

#define Bc   8
#define Lc   256
#define Dc   128
#define Hc   4
#define HDc  32
#define NROW (Bc*Lc)      // 2048
#define RQ   8            // rows per block in qkv GEMM
#define RF   4            // rows per block in ffn
#define NTAU 257

#define TQ   8
#define TK   64
#define PADK 132          // floats per padded smem row (33 float4)
#define NEGV (-4294967295.0f)
#define SCALE 0.17677669529663689f
// dyn smem: sQ 1024 + sKV 8448 + sS 8192 + sW 8224 floats, + tm 2048 + pad 8 ints
#define SMEM_ATTN ((1024 + 8448 + 8192 + 8224)*4 + (2048 + 8)*4)

// ---------------- device scratch ----------------
__device__ __align__(16) float g_seqs[NROW*Dc];
__device__ __align__(16) float g_qin [NROW*Dc];
__device__ __align__(16) float g_Q   [NROW*Dc];
__device__ __align__(16) float g_Kc  [NROW*Dc];   // K + bk + posK
__device__ __align__(16) float g_Vc  [NROW*Dc];   // V + bv + posV
__device__ __align__(16) float g_dqt [NROW*NTAU*4]; // Q . timeK[tau], per head
__device__ __align__(16) float g_W   [NROW*NTAU*4]; // A-histogram over tau, per head

// ---------------- K0: embedding ----------------
__global__ void k_embed(const int* __restrict__ log_seqs,
                        const float* __restrict__ item_emb) {
    int row = blockIdx.x, t = threadIdx.x;
    int idx = log_seqs[row];
    float v = (idx == 0) ? 0.f
                         : item_emb[idx*Dc + t] * 11.313708498984761f; // sqrt(128)
    g_seqs[row*Dc + t] = v;
}

// ---------------- K1a: LN1 per row -> g_qin ----------------
__global__ void k_ln1(const float* __restrict__ g, const float* __restrict__ b) {
    __shared__ float r1[4], r2[4];
    int row = blockIdx.x, t = threadIdx.x;
    int warp = t >> 5, lane = t & 31;
    float x = g_seqs[row*Dc + t];
    float s = x, ss = x*x;
    #pragma unroll
    for (int o = 16; o >= 1; o >>= 1) {
        s  += __shfl_xor_sync(0xffffffffu, s,  o);
        ss += __shfl_xor_sync(0xffffffffu, ss, o);
    }
    if (lane == 0) { r1[warp] = s; r2[warp] = ss; }
    __syncthreads();
    float tot  = r1[0]+r1[1]+r1[2]+r1[3];
    float tots = r2[0]+r2[1]+r2[2]+r2[3];
    float m = tot * (1.f/Dc);
    float inv = rsqrtf(tots * (1.f/Dc) - m*m + 1e-8f);
    g_qin[row*Dc + t] = (x - m) * inv * g[t] + b[t];
}

// ---------------- K1b: QKV projections (blockIdx.y selects matrix) ----------------
__global__ void __launch_bounds__(128) k_qkv(
                      const float* __restrict__ Wq, const float* __restrict__ Wk,
                      const float* __restrict__ Wv,
                      const float* __restrict__ bq, const float* __restrict__ bk,
                      const float* __restrict__ bv,
                      const float* __restrict__ posK, const float* __restrict__ posV) {
    __shared__ __align__(16) float s_x[RQ][Dc];
    int t = threadIdx.x;
    int mat = blockIdx.y;
    int row0 = blockIdx.x * RQ;

    const float* X = (mat == 0) ? g_qin : g_seqs;
    const float* W = (mat == 0) ? Wq : (mat == 1) ? Wk : Wv;
    const float* B = (mat == 0) ? bq : (mat == 1) ? bk : bv;
    float*       O = (mat == 0) ? g_Q : (mat == 1) ? g_Kc : g_Vc;
    const float* P = (mat == 1) ? posK : posV;

    for (int i = t; i < RQ*Dc; i += 128)
        ((float*)s_x)[i] = X[row0*Dc + i];
    __syncthreads();

    float acc[RQ];
    #pragma unroll
    for (int r = 0; r < RQ; ++r) acc[r] = 0.f;

    for (int k = 0; k < Dc; k += 4) {
        float w0 = W[(k+0)*Dc + t], w1 = W[(k+1)*Dc + t];
        float w2 = W[(k+2)*Dc + t], w3 = W[(k+3)*Dc + t];
        #pragma unroll
        for (int r = 0; r < RQ; ++r) {
            float4 x = *(const float4*)&s_x[r][k];
            acc[r] = fmaf(x.x,w0, fmaf(x.y,w1, fmaf(x.z,w2, fmaf(x.w,w3, acc[r]))));
        }
    }

    float bb = B[t];
    #pragma unroll
    for (int r = 0; r < RQ; ++r) {
        int row = row0 + r;
        float p = (mat == 0) ? 0.f : P[(row & (Lc-1))*Dc + t];
        O[row*Dc + t] = acc[r] + bb + p;
    }
}

// ---------------- K1c: dqt[row,tau,h] = Q[row,h,:] . timeK[tau,h,:] ----------------
#define QT_R 16
#define QT_T 32
__global__ void __launch_bounds__(256) k_qt(const float* __restrict__ timeK) {
    __shared__ __align__(16) float sQt[QT_R*128];
    __shared__ __align__(16) float sT [QT_T*PADK];
    int t = threadIdx.x;                  // 256
    int r0   = blockIdx.x * QT_R;
    int tau0 = blockIdx.y * QT_T;

    { // load Q tile: 2048 floats = 512 float4
        const float4* src = (const float4*)&g_Q[r0*128];
        float4* dst = (float4*)sQt;
        dst[t] = src[t]; dst[t+256] = src[t+256];
    }
    { // load timeK tile: up to 1024 float4, padded rows
        const float4* src = (const float4*)&timeK[tau0*128];
        float4* dst = (float4*)sT;
        #pragma unroll
        for (int j = 0; j < 4; ++j) {
            int f4 = t + 256*j;
            int r = f4 >> 5;
            if (tau0 + r < NTAU)
                dst[r*33 + (f4 & 31)] = src[f4];
        }
    }
    __syncthreads();

    int ti = t & 31, rg = t >> 5;
    int tau = tau0 + ti;
    if (tau < NTAU) {
        const float4* tr  = (const float4*)&sT[ti*PADK];
        const float4* qr0 = (const float4*)&sQt[rg*128];
        const float4* qr1 = (const float4*)&sQt[(rg+8)*128];
        float s0[4], s1[4];
        #pragma unroll
        for (int h = 0; h < 4; ++h) { s0[h]=0.f; s1[h]=0.f; }
        #pragma unroll
        for (int h = 0; h < 4; ++h) {
            #pragma unroll
            for (int jj = 0; jj < 8; ++jj) {
                float4 tv = tr[h*8+jj];
                float4 a  = qr0[h*8+jj];
                float4 b  = qr1[h*8+jj];
                s0[h] += tv.x*a.x + tv.y*a.y + tv.z*a.z + tv.w*a.w;
                s1[h] += tv.x*b.x + tv.y*b.y + tv.z*b.z + tv.w*b.w;
            }
        }
        *(float4*)&g_dqt[((size_t)(r0+rg  )*NTAU + tau)*4] = make_float4(s0[0],s0[1],s0[2],s0[3]);
        *(float4*)&g_dqt[((size_t)(r0+rg+8)*NTAU + tau)*4] = make_float4(s1[0],s1[1],s1[2],s1[3]);
    }
}

// ---------------- K2: tiled attention ----------------
__global__ void __launch_bounds__(256) k_attn(const int* __restrict__ log_seqs,
                                              const int* __restrict__ time_mat) {
    extern __shared__ __align__(16) char smem_raw[];
    float* sQ   = (float*)smem_raw;            // TQ*128   = 1024
    float* sKV  = sQ  + 1024;                  // TK*PADK  = 8448
    float* sS   = sKV + 8448;                  // TQ*4*256 = 8192
    float* sW   = sS  + 8192;                  // TQ*4*257 = 8224
    int*   s_tm  = (int*)(sW + 8224);          // TQ*256   = 2048
    int*   s_pad = s_tm + 2048;                // 8

    int t = threadIdx.x;                       // 256
    int b  = blockIdx.x >> 5;
    int q0 = (blockIdx.x & 31) * TQ;
    int row0 = b*Lc + q0;
    int brow = b*Lc;

    { // Q tile: 1024 floats = 256 float4
        const float4* src = (const float4*)&g_Q[row0*128];
        ((float4*)sQ)[t] = src[t];
    }
    { // tm tile: 2048 ints = 512 int4
        const int4* src = (const int4*)&time_mat[row0*256];
        ((int4*)s_tm)[t]       = src[t];
        ((int4*)s_tm)[t + 256] = src[t + 256];
    }
    if (t < TQ) s_pad[t] = (log_seqs[row0 + t] == 0);
    { // init sS=NEG, sW=0
        float4 negv = make_float4(NEGV, NEGV, NEGV, NEGV);
        float4* p = (float4*)sS;
        #pragma unroll
        for (int i = 0; i < 8; ++i) p[t + 256*i] = negv;
        for (int i = t; i < TQ*4*NTAU; i += 256) sW[i] = 0.f;
    }
    __syncthreads();

    int any_pad = s_pad[0]|s_pad[1]|s_pad[2]|s_pad[3]|s_pad[4]|s_pad[5]|s_pad[6]|s_pad[7];
    int qmax = q0 + TQ - 1;
    int nkt = any_pad ? 4 : ((qmax >> 6) + 1);

    // ---- phase 1: scores ----
    for (int kt = 0; kt < nkt; ++kt) {
        int k0 = kt * TK;
        { // load Kc tile: 8192 floats = 2048 float4
            const float4* src = (const float4*)&g_Kc[(brow + k0)*128];
            float4* dst = (float4*)sKV;
            #pragma unroll
            for (int j = 0; j < 8; ++j) {
                int f4 = t + 256*j;
                dst[(f4 >> 5)*33 + (f4 & 31)] = src[f4];
            }
        }
        __syncthreads();
        int kl = t & 63, qq = t >> 6;
        int kg = k0 + kl;
        const float4* kr = (const float4*)&sKV[kl*PADK];
        #pragma unroll
        for (int e = 0; e < 2; ++e) {
            int q = qq + e*4;
            bool masked = s_pad[q] || (kg > q0 + q);
            if (!masked) {
                const float4* qr = (const float4*)&sQ[q*128];
                float sc[4];
                #pragma unroll
                for (int h = 0; h < 4; ++h) {
                    float a = 0.f;
                    #pragma unroll
                    for (int jj = 0; jj < 8; ++jj) {
                        float4 kv = kr[h*8+jj], qv = qr[h*8+jj];
                        a += kv.x*qv.x + kv.y*qv.y + kv.z*qv.z + kv.w*qv.w;
                    }
                    sc[h] = a;
                }
                int tau = s_tm[q*256 + kg];
                float4 dq = *(const float4*)&g_dqt[((size_t)(row0 + q)*NTAU + tau)*4];
                sS[(q*4+0)*256 + kg] = (sc[0] + dq.x) * SCALE;
                sS[(q*4+1)*256 + kg] = (sc[1] + dq.y) * SCALE;
                sS[(q*4+2)*256 + kg] = (sc[2] + dq.z) * SCALE;
                sS[(q*4+3)*256 + kg] = (sc[3] + dq.w) * SCALE;
            }
        }
        __syncthreads();
    }

    // ---- phase 2: softmax per (q,h) combo, one warp handles 4 combos ----
    {
        int w = t >> 5, lane = t & 31;
        #pragma unroll
        for (int j = 0; j < 4; ++j) {
            float* p = sS + (w*4 + j)*256;
            float x[8];
            float mx = -3.4e38f;
            #pragma unroll
            for (int i = 0; i < 8; ++i) { x[i] = p[lane + 32*i]; mx = fmaxf(mx, x[i]); }
            #pragma unroll
            for (int o = 16; o >= 1; o >>= 1)
                mx = fmaxf(mx, __shfl_xor_sync(0xffffffffu, mx, o));
            float s = 0.f;
            #pragma unroll
            for (int i = 0; i < 8; ++i) { x[i] = expf(x[i] - mx); s += x[i]; }
            #pragma unroll
            for (int o = 16; o >= 1; o >>= 1)
                s += __shfl_xor_sync(0xffffffffu, s, o);
            float inv = 1.f / s;
            #pragma unroll
            for (int i = 0; i < 8; ++i) p[lane + 32*i] = x[i] * inv;
        }
    }
    __syncthreads();

    // ---- phase 3: tau-histogram of A (smem atomics, skip zeros) ----
    {
        int k = t;
        #pragma unroll 4
        for (int c = 0; c < 32; ++c) {
            float a = sS[c*256 + k];
            if (a != 0.f) {
                int q = c >> 2;
                int tau = s_tm[q*256 + k];
                atomicAdd(&sW[c*NTAU + tau], a);
            }
        }
    }

    // ---- phase 4: out = A @ Vc ----
    int col = t & 127, qq2 = t >> 7;
    int h = col >> 5;
    float acc[4] = {0.f, 0.f, 0.f, 0.f};
    for (int kt = 0; kt < nkt; ++kt) {
        int k0 = kt * TK;
        __syncthreads();
        {
            const float4* src = (const float4*)&g_Vc[(brow + k0)*128];
            float4* dst = (float4*)sKV;
            #pragma unroll
            for (int j = 0; j < 8; ++j) {
                int f4 = t + 256*j;
                dst[(f4 >> 5)*33 + (f4 & 31)] = src[f4];
            }
        }
        __syncthreads();
        for (int k = 0; k < TK; ++k) {
            float v = sKV[k*PADK + col];
            #pragma unroll
            for (int e = 0; e < 4; ++e) {
                int q = qq2 + e*2;
                acc[e] = fmaf(sS[(q*4+h)*256 + k0 + k], v, acc[e]);
            }
        }
    }
    #pragma unroll
    for (int e = 0; e < 4; ++e) {
        int q = qq2 + e*2;
        int idx = (row0 + q)*128 + col;
        g_seqs[idx] = g_qin[idx] + acc[e];
    }
    __syncthreads();
    // ---- write histogram to global ----
    for (int i = t; i < TQ*4*NTAU; i += 256) {
        int q = i / (4*NTAU);
        g_W[(row0 + q)*(4*NTAU) + (i - q*(4*NTAU))] = sW[i];
    }
}

// ---------------- K2b: seqs += W @ timeV ----------------
__global__ void __launch_bounds__(128) k_av2(const float* __restrict__ timeV) {
    int t = threadIdx.x;                  // 128
    int r0 = blockIdx.x * 8;
    int h = t >> 5;
    float acc[8];
    #pragma unroll
    for (int r = 0; r < 8; ++r) acc[r] = 0.f;
    const float* Wp = &g_W[(size_t)r0*(4*NTAU) + h*NTAU];
    for (int tau = 0; tau < NTAU; ++tau) {
        float v = timeV[tau*128 + t];
        #pragma unroll
        for (int r = 0; r < 8; ++r)
            acc[r] = fmaf(Wp[r*(4*NTAU) + tau], v, acc[r]);
    }
    #pragma unroll
    for (int r = 0; r < 8; ++r)
        g_seqs[(r0 + r)*128 + t] += acc[r];
}

// ---------------- K3: LN2 + FFN + residual + pad-mask ----------------
__global__ void __launch_bounds__(128) k_ffn(const int* __restrict__ log_seqs,
                      const float* __restrict__ ln2_g, const float* __restrict__ ln2_b,
                      const float* __restrict__ W1, const float* __restrict__ b1,
                      const float* __restrict__ W2, const float* __restrict__ b2) {
    __shared__ __align__(16) float s_y[RF][Dc];
    __shared__ __align__(16) float s_h[RF][Dc];
    __shared__ float s_mean[RF], s_inv[RF];
    __shared__ int   s_pad[RF];
    int t = threadIdx.x;
    int row0 = blockIdx.x * RF;
    int r = t >> 5, lane = t & 31;

    for (int i = t; i < RF*Dc; i += 128)
        ((float*)s_h)[i] = g_seqs[row0*Dc + i];
    if (t < RF) s_pad[t] = (log_seqs[row0 + t] == 0);
    __syncthreads();

    {
        float4 v4 = *(const float4*)&s_h[r][lane*4];
        float s  = v4.x + v4.y + v4.z + v4.w;
        float ss = v4.x*v4.x + v4.y*v4.y + v4.z*v4.z + v4.w*v4.w;
        #pragma unroll
        for (int o = 16; o >= 1; o >>= 1) {
            s  += __shfl_xor_sync(0xffffffffu, s,  o);
            ss += __shfl_xor_sync(0xffffffffu, ss, o);
        }
        if (lane == 0) {
            float m = s * (1.f/Dc);
            float var = ss * (1.f/Dc) - m*m;
            s_mean[r] = m;
            s_inv[r]  = rsqrtf(var + 1e-8f);
        }
    }
    __syncthreads();

    float g = ln2_g[t], bb = ln2_b[t];
    #pragma unroll
    for (int rr = 0; rr < RF; ++rr)
        s_y[rr][t] = (s_h[rr][t] - s_mean[rr]) * s_inv[rr] * g + bb;
    __syncthreads();

    float a1[RF];
    #pragma unroll
    for (int rr = 0; rr < RF; ++rr) a1[rr] = 0.f;
    for (int k = 0; k < Dc; k += 4) {
        float w0=W1[(k+0)*Dc+t], w1=W1[(k+1)*Dc+t], w2=W1[(k+2)*Dc+t], w3=W1[(k+3)*Dc+t];
        #pragma unroll
        for (int rr = 0; rr < RF; ++rr) {
            float4 y = *(const float4*)&s_y[rr][k];
            a1[rr] = fmaf(y.x,w0, fmaf(y.y,w1, fmaf(y.z,w2, fmaf(y.w,w3, a1[rr]))));
        }
    }
    float b1v = b1[t];
    __syncthreads();
    #pragma unroll
    for (int rr = 0; rr < RF; ++rr)
        s_h[rr][t] = fmaxf(a1[rr] + b1v, 0.f);
    __syncthreads();

    float a2[RF];
    #pragma unroll
    for (int rr = 0; rr < RF; ++rr) a2[rr] = 0.f;
    for (int k = 0; k < Dc; k += 4) {
        float w0=W2[(k+0)*Dc+t], w1=W2[(k+1)*Dc+t], w2=W2[(k+2)*Dc+t], w3=W2[(k+3)*Dc+t];
        #pragma unroll
        for (int rr = 0; rr < RF; ++rr) {
            float4 h4 = *(const float4*)&s_h[rr][k];
            a2[rr] = fmaf(h4.x,w0, fmaf(h4.y,w1, fmaf(h4.z,w2, fmaf(h4.w,w3, a2[rr]))));
        }
    }
    float b2v = b2[t];
    #pragma unroll
    for (int rr = 0; rr < RF; ++rr) {
        float v = s_y[rr][t] + a2[rr] + b2v;
        g_seqs[(row0 + rr)*Dc + t] = s_pad[rr] ? 0.f : v;
    }
}

// ---------------- K4: final LN + pos/neg logits ----------------
__global__ void __launch_bounds__(128) k_logits(
                         const int* __restrict__ pos_seqs, const int* __restrict__ neg_seqs,
                         const float* __restrict__ item_emb,
                         const float* __restrict__ lnf_g, const float* __restrict__ lnf_b,
                         float* __restrict__ out) {
    __shared__ float r1[4], r2[4];
    int row = blockIdx.x, t = threadIdx.x;
    int warp = t >> 5, lane = t & 31;

    float x = g_seqs[row*Dc + t];
    float s = x, ss = x*x;
    #pragma unroll
    for (int o = 16; o >= 1; o >>= 1) {
        s  += __shfl_xor_sync(0xffffffffu, s,  o);
        ss += __shfl_xor_sync(0xffffffffu, ss, o);
    }
    if (lane == 0) { r1[warp] = s; r2[warp] = ss; }
    __syncthreads();
    float tot  = r1[0]+r1[1]+r1[2]+r1[3];
    float tots = r2[0]+r2[1]+r2[2]+r2[3];
    float m = tot * (1.f/Dc);
    float inv = rsqrtf(tots * (1.f/Dc) - m*m + 1e-8f);
    float f = (x - m) * inv * lnf_g[t] + lnf_b[t];

    int pi = pos_seqs[row], ni = neg_seqs[row];
    float pp = f * item_emb[pi*Dc + t];
    float nn = f * item_emb[ni*Dc + t];
    #pragma unroll
    for (int o = 16; o >= 1; o >>= 1) {
        pp += __shfl_xor_sync(0xffffffffu, pp, o);
        nn += __shfl_xor_sync(0xffffffffu, nn, o);
    }
    __syncthreads();
    if (lane == 0) { r1[warp] = pp; r2[warp] = nn; }
    __syncthreads();
    if (t == 0) {
        out[row]        = r1[0]+r1[1]+r1[2]+r1[3];
        out[NROW + row] = r2[0]+r2[1]+r2[2]+r2[3];
    }
}

// ---------------- launch ----------------
extern "C" void kernel_launch(void* const* d_in, const int* in_sizes, int n_in,
                              void* d_out, int out_size) {
    const int*   log_seqs = (const int*)  d_in[1];
    const int*   time_mat = (const int*)  d_in[2];
    const int*   pos_seqs = (const int*)  d_in[3];
    const int*   neg_seqs = (const int*)  d_in[4];
    const float* item_emb = (const float*)d_in[5];
    const float* posK     = (const float*)d_in[6];
    const float* posV     = (const float*)d_in[7];
    const float* timeK    = (const float*)d_in[8];
    const float* timeV    = (const float*)d_in[9];
    const float* ln1_g    = (const float*)d_in[10];
    const float* ln1_b    = (const float*)d_in[11];
    const float* Wq       = (const float*)d_in[12];
    const float* bq       = (const float*)d_in[13];
    const float* Wk       = (const float*)d_in[14];
    const float* bk       = (const float*)d_in[15];
    const float* Wv       = (const float*)d_in[16];
    const float* bv       = (const float*)d_in[17];
    const float* ln2_g    = (const float*)d_in[18];
    const float* ln2_b    = (const float*)d_in[19];
    const float* W1       = (const float*)d_in[20];
    const float* b1       = (const float*)d_in[21];
    const float* W2       = (const float*)d_in[22];
    const float* b2       = (const float*)d_in[23];
    const float* lnf_g    = (const float*)d_in[24];
    const float* lnf_b    = (const float*)d_in[25];
    float* out = (float*)d_out;

    cudaFuncSetAttribute(k_attn, cudaFuncAttributeMaxDynamicSharedMemorySize, SMEM_ATTN);

    k_embed<<<NROW, 128>>>(log_seqs, item_emb);
    for (int i = 0; i < 2; ++i) {
        k_ln1<<<NROW, 128>>>(ln1_g + i*Dc, ln1_b + i*Dc);
        dim3 gq(NROW/RQ, 3);
        k_qkv<<<gq, 128>>>(Wq + i*Dc*Dc, Wk + i*Dc*Dc, Wv + i*Dc*Dc,
                           bq + i*Dc, bk + i*Dc, bv + i*Dc, posK, posV);
        dim3 gt(NROW/QT_R, (NTAU + QT_T - 1)/QT_T);
        k_qt<<<gt, 256>>>(timeK);
        k_attn<<<NROW/TQ, 256, SMEM_ATTN>>>(log_seqs, time_mat);
        k_av2<<<NROW/8, 128>>>(timeV);
        k_ffn<<<NROW/RF, 128>>>(log_seqs, ln2_g + i*Dc, ln2_b + i*Dc,
                                W1 + i*Dc*Dc, b1 + i*Dc,
                                W2 + i*Dc*Dc, b2 + i*Dc);
    }
    k_logits<<<NROW, 128>>>(pos_seqs, neg_seqs, item_emb, lnf_g, lnf_b, out);
}

// round 5
// speedup vs baseline: 1.5346x; 1.5346x over previous
#include <cuda_runtime.h>
#include <math.h>

#define Bc   8
#define Lc   256
#define Dc   128
#define Hc   4
#define HDc  32
#define NROW (Bc*Lc)      // 2048
#define RQ   8            // rows per block in qkv GEMM
#define RF   4            // rows per block in ffn
#define NTAU 257

#define TQ2  4            // queries per attention block
#define CH   64           // key chunk
#define PADK 132          // floats per padded smem row (33 float4)
#define NEGV (-4294967295.0f)
#define SCALE 0.17677669529663689f
// dyn smem floats: sKV 8448 + sQ 512 + sS 4096 = 13056; ints: tm 1024 + pad 4
#define SMEM_ATTN (13056*4 + 1028*4 + 16)

// ---------------- device scratch ----------------
__device__ __align__(16) float g_seqs[NROW*Dc];
__device__ __align__(16) float g_qin [NROW*Dc];
__device__ __align__(16) float g_Q   [NROW*Dc];
__device__ __align__(16) float g_Kc  [NROW*Dc];   // K + bk + posK
__device__ __align__(16) float g_Vc  [NROW*Dc];   // V + bv + posV
__device__ __align__(16) float g_dqt [NROW*NTAU*4]; // Q . timeK[tau], per head

// ---------------- K0: embedding ----------------
__global__ void k_embed(const int* __restrict__ log_seqs,
                        const float* __restrict__ item_emb) {
    int row = blockIdx.x, t = threadIdx.x;
    int idx = log_seqs[row];
    float v = (idx == 0) ? 0.f
                         : item_emb[idx*Dc + t] * 11.313708498984761f; // sqrt(128)
    g_seqs[row*Dc + t] = v;
}

// ---------------- K1a: LN1 per row -> g_qin ----------------
__global__ void k_ln1(const float* __restrict__ g, const float* __restrict__ b) {
    __shared__ float r1[4], r2[4];
    int row = blockIdx.x, t = threadIdx.x;
    int warp = t >> 5, lane = t & 31;
    float x = g_seqs[row*Dc + t];
    float s = x, ss = x*x;
    #pragma unroll
    for (int o = 16; o >= 1; o >>= 1) {
        s  += __shfl_xor_sync(0xffffffffu, s,  o);
        ss += __shfl_xor_sync(0xffffffffu, ss, o);
    }
    if (lane == 0) { r1[warp] = s; r2[warp] = ss; }
    __syncthreads();
    float tot  = r1[0]+r1[1]+r1[2]+r1[3];
    float tots = r2[0]+r2[1]+r2[2]+r2[3];
    float m = tot * (1.f/Dc);
    float inv = rsqrtf(tots * (1.f/Dc) - m*m + 1e-8f);
    g_qin[row*Dc + t] = (x - m) * inv * g[t] + b[t];
}

// ---------------- K1b: QKV projections (blockIdx.y selects matrix) ----------------
__global__ void __launch_bounds__(128) k_qkv(
                      const float* __restrict__ Wq, const float* __restrict__ Wk,
                      const float* __restrict__ Wv,
                      const float* __restrict__ bq, const float* __restrict__ bk,
                      const float* __restrict__ bv,
                      const float* __restrict__ posK, const float* __restrict__ posV) {
    __shared__ __align__(16) float s_x[RQ][Dc];
    int t = threadIdx.x;
    int mat = blockIdx.y;
    int row0 = blockIdx.x * RQ;

    const float* X = (mat == 0) ? g_qin : g_seqs;
    const float* W = (mat == 0) ? Wq : (mat == 1) ? Wk : Wv;
    const float* B = (mat == 0) ? bq : (mat == 1) ? bk : bv;
    float*       O = (mat == 0) ? g_Q : (mat == 1) ? g_Kc : g_Vc;
    const float* P = (mat == 1) ? posK : posV;

    for (int i = t; i < RQ*Dc; i += 128)
        ((float*)s_x)[i] = X[row0*Dc + i];
    __syncthreads();

    float acc[RQ];
    #pragma unroll
    for (int r = 0; r < RQ; ++r) acc[r] = 0.f;

    for (int k = 0; k < Dc; k += 4) {
        float w0 = W[(k+0)*Dc + t], w1 = W[(k+1)*Dc + t];
        float w2 = W[(k+2)*Dc + t], w3 = W[(k+3)*Dc + t];
        #pragma unroll
        for (int r = 0; r < RQ; ++r) {
            float4 x = *(const float4*)&s_x[r][k];
            acc[r] = fmaf(x.x,w0, fmaf(x.y,w1, fmaf(x.z,w2, fmaf(x.w,w3, acc[r]))));
        }
    }

    float bb = B[t];
    #pragma unroll
    for (int r = 0; r < RQ; ++r) {
        int row = row0 + r;
        float p = (mat == 0) ? 0.f : P[(row & (Lc-1))*Dc + t];
        O[row*Dc + t] = acc[r] + bb + p;
    }
}

// ---------------- K1c: dqt[row,tau,h] = Q[row,h,:] . timeK[tau,h,:] ----------------
// thread = (tau, head): timeK segment held in REGISTERS; Q broadcast from smem.
#define QTROWS 128
#define QTCH   32
__global__ void __launch_bounds__(256) k_qt(const float* __restrict__ timeK) {
    __shared__ __align__(16) float sQ[QTCH*128];   // 16 KB
    int t = threadIdx.x;
    int w = t >> 5, lane = t & 31;
    int h = w & 3;
    int tau = blockIdx.y*64 + (w >> 2)*32 + lane;
    int r0 = blockIdx.x * QTROWS;
    bool valid = (tau < NTAU);

    float4 tr[8];
    if (valid) {
        const float4* src = (const float4*)&timeK[tau*128 + h*32];
        #pragma unroll
        for (int j = 0; j < 8; ++j) tr[j] = src[j];
    }

    for (int c = 0; c < QTROWS; c += QTCH) {
        __syncthreads();
        { // stage 32 Q rows (coalesced)
            const float4* src = (const float4*)&g_Q[(r0 + c)*128];
            float4* dst = (float4*)sQ;
            #pragma unroll
            for (int j = 0; j < 4; ++j) dst[t + 256*j] = src[t + 256*j];
        }
        __syncthreads();
        if (valid) {
            for (int r = 0; r < QTCH; ++r) {
                const float4* qp = (const float4*)&sQ[r*128 + h*32]; // broadcast
                float a = 0.f;
                #pragma unroll
                for (int j = 0; j < 8; ++j) {
                    float4 q4 = qp[j];
                    a += tr[j].x*q4.x + tr[j].y*q4.y + tr[j].z*q4.z + tr[j].w*q4.w;
                }
                g_dqt[((size_t)(r0 + c + r)*NTAU + tau)*4 + h] = a;
            }
        }
    }
}

// ---------------- K2: tiled attention (TQ2 queries/block, smem-staged K/V) ----------------
__global__ void __launch_bounds__(256) k_attn(const int* __restrict__ log_seqs,
                                              const int* __restrict__ time_mat,
                                              const float* __restrict__ timeV) {
    extern __shared__ __align__(16) char smem_raw[];
    float* sKV = (float*)smem_raw;                 // CH*PADK = 8448
    float* sQ  = sKV + 8448;                       // TQ2*128 = 512
    float* sS  = sQ  + 512;                        // TQ2*4*256 = 4096
    int*   s_tm  = (int*)(sS + 4096);              // TQ2*256 = 1024
    int*   s_pad = s_tm + 1024;                    // 4

    int t = threadIdx.x;                           // 256
    int b  = blockIdx.x >> 6;
    int q0 = (blockIdx.x & 63) * TQ2;
    int row0 = b*Lc + q0;
    int brow = b*Lc;

    { // Q tile: 512 floats = 128 float4
        if (t < 128) {
            const float4* src = (const float4*)&g_Q[row0*128];
            ((float4*)sQ)[t] = src[t];
        }
    }
    { // tm tile: 1024 ints = 256 int4
        const int4* src = (const int4*)&time_mat[row0*256];
        ((int4*)s_tm)[t] = src[t];
    }
    if (t < TQ2) s_pad[t] = (log_seqs[row0 + t] == 0);
    { // init sS = NEGV
        float4 negv = make_float4(NEGV, NEGV, NEGV, NEGV);
        float4* p = (float4*)sS;
        #pragma unroll
        for (int i = 0; i < 4; ++i) p[t + 256*i] = negv;
    }
    __syncthreads();

    int nkt = ((q0 + TQ2 - 1) >> 6) + 1;

    // ---- pass 1: scores ----
    int q = t >> 6, kl = t & 63;
    for (int kt = 0; kt < nkt; ++kt) {
        int k0 = kt * CH;
        { // coalesced load Kc chunk: 2048 float4
            const float4* src = (const float4*)&g_Kc[(brow + k0)*128];
            float4* dst = (float4*)sKV;
            #pragma unroll
            for (int j = 0; j < 8; ++j) {
                int f4 = t + 256*j;
                dst[(f4 >> 5)*33 + (f4 & 31)] = src[f4];
            }
        }
        __syncthreads();
        int kg = k0 + kl;
        if (!s_pad[q] && kg <= q0 + q) {
            const float4* kr = (const float4*)&sKV[kl*PADK];
            const float4* qr = (const float4*)&sQ[q*128];   // broadcast
            float sc[4] = {0.f, 0.f, 0.f, 0.f};
            #pragma unroll
            for (int j = 0; j < 32; ++j) {
                float4 kv = kr[j], qv = qr[j];
                sc[j >> 3] += kv.x*qv.x + kv.y*qv.y + kv.z*qv.z + kv.w*qv.w;
            }
            int tau = s_tm[q*256 + kg];
            float4 dq = *(const float4*)&g_dqt[((size_t)(row0 + q)*NTAU + tau)*4];
            sS[(q*4+0)*256 + kg] = (sc[0] + dq.x) * SCALE;
            sS[(q*4+1)*256 + kg] = (sc[1] + dq.y) * SCALE;
            sS[(q*4+2)*256 + kg] = (sc[2] + dq.z) * SCALE;
            sS[(q*4+3)*256 + kg] = (sc[3] + dq.w) * SCALE;
        }
        __syncthreads();
    }

    // ---- pass 2: softmax (16 rows of 256; each warp handles 2 rows) ----
    {
        int w = t >> 5, lane = t & 31;
        #pragma unroll
        for (int j = 0; j < 2; ++j) {
            float* p = sS + (w + j*8)*256;
            float x[8];
            float mx = -3.4e38f;
            #pragma unroll
            for (int i = 0; i < 8; ++i) { x[i] = p[lane + 32*i]; mx = fmaxf(mx, x[i]); }
            #pragma unroll
            for (int o = 16; o >= 1; o >>= 1)
                mx = fmaxf(mx, __shfl_xor_sync(0xffffffffu, mx, o));
            float s = 0.f;
            #pragma unroll
            for (int i = 0; i < 8; ++i) { x[i] = expf(x[i] - mx); s += x[i]; }
            #pragma unroll
            for (int o = 16; o >= 1; o >>= 1)
                s += __shfl_xor_sync(0xffffffffu, s, o);
            float inv = 1.f / s;
            #pragma unroll
            for (int i = 0; i < 8; ++i) p[lane + 32*i] = x[i] * inv;
        }
    }
    __syncthreads();

    // ---- pass 3: out = A @ (Vc, timeV) ----
    int col = t & 127, qp = t >> 7;     // q in {qp, qp+2}
    int h = col >> 5;
    float acc0 = 0.f, acc1 = 0.f;
    for (int kt = 0; kt < nkt; ++kt) {
        int k0 = kt * CH;
        __syncthreads();
        { // coalesced load Vc chunk
            const float4* src = (const float4*)&g_Vc[(brow + k0)*128];
            float4* dst = (float4*)sKV;
            #pragma unroll
            for (int j = 0; j < 8; ++j) {
                int f4 = t + 256*j;
                dst[(f4 >> 5)*33 + (f4 & 31)] = src[f4];
            }
        }
        __syncthreads();
        for (int k = 0; k < CH; ++k) {
            int kg = k0 + k;
            float v = sKV[k*PADK + col];
            float a0 = sS[(qp*4 + h)*256 + kg];          // broadcast
            if (a0 != 0.f) {                              // uniform branch per warp
                float tv = timeV[s_tm[qp*256 + kg]*128 + col];   // 128B coalesced
                acc0 = fmaf(a0, v + tv, acc0);
            }
            float a1 = sS[((qp+2)*4 + h)*256 + kg];
            if (a1 != 0.f) {
                float tv = timeV[s_tm[(qp+2)*256 + kg]*128 + col];
                acc1 = fmaf(a1, v + tv, acc1);
            }
        }
    }
    {
        int i0 = (row0 + qp)*128 + col;
        int i1 = (row0 + qp + 2)*128 + col;
        g_seqs[i0] = g_qin[i0] + acc0;
        g_seqs[i1] = g_qin[i1] + acc1;
    }
}

// ---------------- K3: LN2 + FFN + residual + pad-mask ----------------
__global__ void __launch_bounds__(128) k_ffn(const int* __restrict__ log_seqs,
                      const float* __restrict__ ln2_g, const float* __restrict__ ln2_b,
                      const float* __restrict__ W1, const float* __restrict__ b1,
                      const float* __restrict__ W2, const float* __restrict__ b2) {
    __shared__ __align__(16) float s_y[RF][Dc];
    __shared__ __align__(16) float s_h[RF][Dc];
    __shared__ float s_mean[RF], s_inv[RF];
    __shared__ int   s_pad[RF];
    int t = threadIdx.x;
    int row0 = blockIdx.x * RF;
    int r = t >> 5, lane = t & 31;

    for (int i = t; i < RF*Dc; i += 128)
        ((float*)s_h)[i] = g_seqs[row0*Dc + i];
    if (t < RF) s_pad[t] = (log_seqs[row0 + t] == 0);
    __syncthreads();

    {
        float4 v4 = *(const float4*)&s_h[r][lane*4];
        float s  = v4.x + v4.y + v4.z + v4.w;
        float ss = v4.x*v4.x + v4.y*v4.y + v4.z*v4.z + v4.w*v4.w;
        #pragma unroll
        for (int o = 16; o >= 1; o >>= 1) {
            s  += __shfl_xor_sync(0xffffffffu, s,  o);
            ss += __shfl_xor_sync(0xffffffffu, ss, o);
        }
        if (lane == 0) {
            float m = s * (1.f/Dc);
            float var = ss * (1.f/Dc) - m*m;
            s_mean[r] = m;
            s_inv[r]  = rsqrtf(var + 1e-8f);
        }
    }
    __syncthreads();

    float g = ln2_g[t], bb = ln2_b[t];
    #pragma unroll
    for (int rr = 0; rr < RF; ++rr)
        s_y[rr][t] = (s_h[rr][t] - s_mean[rr]) * s_inv[rr] * g + bb;
    __syncthreads();

    float a1[RF];
    #pragma unroll
    for (int rr = 0; rr < RF; ++rr) a1[rr] = 0.f;
    for (int k = 0; k < Dc; k += 4) {
        float w0=W1[(k+0)*Dc+t], w1=W1[(k+1)*Dc+t], w2=W1[(k+2)*Dc+t], w3=W1[(k+3)*Dc+t];
        #pragma unroll
        for (int rr = 0; rr < RF; ++rr) {
            float4 y = *(const float4*)&s_y[rr][k];
            a1[rr] = fmaf(y.x,w0, fmaf(y.y,w1, fmaf(y.z,w2, fmaf(y.w,w3, a1[rr]))));
        }
    }
    float b1v = b1[t];
    __syncthreads();
    #pragma unroll
    for (int rr = 0; rr < RF; ++rr)
        s_h[rr][t] = fmaxf(a1[rr] + b1v, 0.f);
    __syncthreads();

    float a2[RF];
    #pragma unroll
    for (int rr = 0; rr < RF; ++rr) a2[rr] = 0.f;
    for (int k = 0; k < Dc; k += 4) {
        float w0=W2[(k+0)*Dc+t], w1=W2[(k+1)*Dc+t], w2=W2[(k+2)*Dc+t], w3=W2[(k+3)*Dc+t];
        #pragma unroll
        for (int rr = 0; rr < RF; ++rr) {
            float4 h4 = *(const float4*)&s_h[rr][k];
            a2[rr] = fmaf(h4.x,w0, fmaf(h4.y,w1, fmaf(h4.z,w2, fmaf(h4.w,w3, a2[rr]))));
        }
    }
    float b2v = b2[t];
    #pragma unroll
    for (int rr = 0; rr < RF; ++rr) {
        float v = s_y[rr][t] + a2[rr] + b2v;
        g_seqs[(row0 + rr)*Dc + t] = s_pad[rr] ? 0.f : v;
    }
}

// ---------------- K4: final LN + pos/neg logits ----------------
__global__ void __launch_bounds__(128) k_logits(
                         const int* __restrict__ pos_seqs, const int* __restrict__ neg_seqs,
                         const float* __restrict__ item_emb,
                         const float* __restrict__ lnf_g, const float* __restrict__ lnf_b,
                         float* __restrict__ out) {
    __shared__ float r1[4], r2[4];
    int row = blockIdx.x, t = threadIdx.x;
    int warp = t >> 5, lane = t & 31;

    float x = g_seqs[row*Dc + t];
    float s = x, ss = x*x;
    #pragma unroll
    for (int o = 16; o >= 1; o >>= 1) {
        s  += __shfl_xor_sync(0xffffffffu, s,  o);
        ss += __shfl_xor_sync(0xffffffffu, ss, o);
    }
    if (lane == 0) { r1[warp] = s; r2[warp] = ss; }
    __syncthreads();
    float tot  = r1[0]+r1[1]+r1[2]+r1[3];
    float tots = r2[0]+r2[1]+r2[2]+r2[3];
    float m = tot * (1.f/Dc);
    float inv = rsqrtf(tots * (1.f/Dc) - m*m + 1e-8f);
    float f = (x - m) * inv * lnf_g[t] + lnf_b[t];

    int pi = pos_seqs[row], ni = neg_seqs[row];
    float pp = f * item_emb[pi*Dc + t];
    float nn = f * item_emb[ni*Dc + t];
    #pragma unroll
    for (int o = 16; o >= 1; o >>= 1) {
        pp += __shfl_xor_sync(0xffffffffu, pp, o);
        nn += __shfl_xor_sync(0xffffffffu, nn, o);
    }
    __syncthreads();
    if (lane == 0) { r1[warp] = pp; r2[warp] = nn; }
    __syncthreads();
    if (t == 0) {
        out[row]        = r1[0]+r1[1]+r1[2]+r1[3];
        out[NROW + row] = r2[0]+r2[1]+r2[2]+r2[3];
    }
}

// ---------------- launch ----------------
extern "C" void kernel_launch(void* const* d_in, const int* in_sizes, int n_in,
                              void* d_out, int out_size) {
    const int*   log_seqs = (const int*)  d_in[1];
    const int*   time_mat = (const int*)  d_in[2];
    const int*   pos_seqs = (const int*)  d_in[3];
    const int*   neg_seqs = (const int*)  d_in[4];
    const float* item_emb = (const float*)d_in[5];
    const float* posK     = (const float*)d_in[6];
    const float* posV     = (const float*)d_in[7];
    const float* timeK    = (const float*)d_in[8];
    const float* timeV    = (const float*)d_in[9];
    const float* ln1_g    = (const float*)d_in[10];
    const float* ln1_b    = (const float*)d_in[11];
    const float* Wq       = (const float*)d_in[12];
    const float* bq       = (const float*)d_in[13];
    const float* Wk       = (const float*)d_in[14];
    const float* bk       = (const float*)d_in[15];
    const float* Wv       = (const float*)d_in[16];
    const float* bv       = (const float*)d_in[17];
    const float* ln2_g    = (const float*)d_in[18];
    const float* ln2_b    = (const float*)d_in[19];
    const float* W1       = (const float*)d_in[20];
    const float* b1       = (const float*)d_in[21];
    const float* W2       = (const float*)d_in[22];
    const float* b2       = (const float*)d_in[23];
    const float* lnf_g    = (const float*)d_in[24];
    const float* lnf_b    = (const float*)d_in[25];
    float* out = (float*)d_out;

    cudaFuncSetAttribute(k_attn, cudaFuncAttributeMaxDynamicSharedMemorySize, SMEM_ATTN);

    k_embed<<<NROW, 128>>>(log_seqs, item_emb);
    for (int i = 0; i < 2; ++i) {
        k_ln1<<<NROW, 128>>>(ln1_g + i*Dc, ln1_b + i*Dc);
        dim3 gq(NROW/RQ, 3);
        k_qkv<<<gq, 128>>>(Wq + i*Dc*Dc, Wk + i*Dc*Dc, Wv + i*Dc*Dc,
                           bq + i*Dc, bk + i*Dc, bv + i*Dc, posK, posV);
        dim3 gt(NROW/QTROWS, 5);          // (16, 5): 64 taus per y-block
        k_qt<<<gt, 256>>>(timeK);
        k_attn<<<NROW/TQ2, 256, SMEM_ATTN>>>(log_seqs, time_mat, timeV);
        k_ffn<<<NROW/RF, 128>>>(log_seqs, ln2_g + i*Dc, ln2_b + i*Dc,
                                W1 + i*Dc*Dc, b1 + i*Dc,
                                W2 + i*Dc*Dc, b2 + i*Dc);
    }
    k_logits<<<NROW, 128>>>(pos_seqs, neg_seqs, item_emb, lnf_g, lnf_b, out);
}

// round 6
// speedup vs baseline: 1.6371x; 1.0668x over previous
#include <cuda_runtime.h>
#include <cuda_bf16.h>
#include <math.h>

#define Bc   8
#define Lc   256
#define Dc   128
#define Hc   4
#define HDc  32
#define NROW (Bc*Lc)      // 2048
#define RQ   8            // rows per block in qkv GEMM
#define RF   4            // rows per block in ffn
#define NTAU 257

#define TQ2  4            // queries per attention block
#define CH   64           // key chunk
#define PADK 132          // floats per padded smem row (33 float4)
#define NEGV (-4294967295.0f)
#define SCALE 0.17677669529663689f
// dyn smem floats: sKV 8448 + sQ 512 + sS 4096 = 13056; ints: tm 1024 + pad 4
#define SMEM_ATTN (13056*4 + 1028*4 + 16)

// ---------------- device scratch ----------------
__device__ __align__(16) float g_seqs[NROW*Dc];
__device__ __align__(16) float g_qin [NROW*Dc];
__device__ __align__(16) float g_Q   [NROW*Dc];
__device__ __align__(16) float g_Kc  [NROW*Dc];   // K + bk + posK
__device__ __align__(16) float g_Vc  [NROW*Dc];   // V + bv + posV
__device__ __align__(16) float g_dqt [NROW*NTAU*4]; // Q . timeK[tau], per head
__device__ __align__(16) __nv_bfloat16 g_tVb[NTAU*Dc]; // bf16 copy of timeV

// ---------------- K-1: bf16 conversion of timeV ----------------
__global__ void k_cvt(const float* __restrict__ timeV) {
    int i = blockIdx.x*256 + threadIdx.x;
    if (i < NTAU*Dc) g_tVb[i] = __float2bfloat16(timeV[i]);
}

// ---------------- K0: embedding + LN1(layer 0) ----------------
__global__ void __launch_bounds__(128) k_embed(const int* __restrict__ log_seqs,
                        const float* __restrict__ item_emb,
                        const float* __restrict__ g1, const float* __restrict__ b1) {
    __shared__ float r1[4], r2[4];
    int row = blockIdx.x, t = threadIdx.x;
    int warp = t >> 5, lane = t & 31;
    int idx = log_seqs[row];
    float v = (idx == 0) ? 0.f
                         : item_emb[idx*Dc + t] * 11.313708498984761f; // sqrt(128)
    g_seqs[row*Dc + t] = v;
    float s = v, ss = v*v;
    #pragma unroll
    for (int o = 16; o >= 1; o >>= 1) {
        s  += __shfl_xor_sync(0xffffffffu, s,  o);
        ss += __shfl_xor_sync(0xffffffffu, ss, o);
    }
    if (lane == 0) { r1[warp] = s; r2[warp] = ss; }
    __syncthreads();
    float tot  = r1[0]+r1[1]+r1[2]+r1[3];
    float tots = r2[0]+r2[1]+r2[2]+r2[3];
    float m = tot * (1.f/Dc);
    float inv = rsqrtf(tots * (1.f/Dc) - m*m + 1e-8f);
    g_qin[row*Dc + t] = (v - m) * inv * g1[t] + b1[t];
}

// ---------------- K1b: QKV projections (blockIdx.y selects matrix) ----------------
__global__ void __launch_bounds__(128) k_qkv(
                      const float* __restrict__ Wq, const float* __restrict__ Wk,
                      const float* __restrict__ Wv,
                      const float* __restrict__ bq, const float* __restrict__ bk,
                      const float* __restrict__ bv,
                      const float* __restrict__ posK, const float* __restrict__ posV) {
    __shared__ __align__(16) float s_x[RQ][Dc];
    int t = threadIdx.x;
    int mat = blockIdx.y;
    int row0 = blockIdx.x * RQ;

    const float* X = (mat == 0) ? g_qin : g_seqs;
    const float* W = (mat == 0) ? Wq : (mat == 1) ? Wk : Wv;
    const float* B = (mat == 0) ? bq : (mat == 1) ? bk : bv;
    float*       O = (mat == 0) ? g_Q : (mat == 1) ? g_Kc : g_Vc;
    const float* P = (mat == 1) ? posK : posV;

    for (int i = t; i < RQ*Dc; i += 128)
        ((float*)s_x)[i] = X[row0*Dc + i];
    __syncthreads();

    float acc[RQ];
    #pragma unroll
    for (int r = 0; r < RQ; ++r) acc[r] = 0.f;

    for (int k = 0; k < Dc; k += 4) {
        float w0 = W[(k+0)*Dc + t], w1 = W[(k+1)*Dc + t];
        float w2 = W[(k+2)*Dc + t], w3 = W[(k+3)*Dc + t];
        #pragma unroll
        for (int r = 0; r < RQ; ++r) {
            float4 x = *(const float4*)&s_x[r][k];
            acc[r] = fmaf(x.x,w0, fmaf(x.y,w1, fmaf(x.z,w2, fmaf(x.w,w3, acc[r]))));
        }
    }

    float bb = B[t];
    #pragma unroll
    for (int r = 0; r < RQ; ++r) {
        int row = row0 + r;
        float p = (mat == 0) ? 0.f : P[(row & (Lc-1))*Dc + t];
        O[row*Dc + t] = acc[r] + bb + p;
    }
}

// ---------------- K1c: dqt[row,tau,h] = Q[row,h,:] . timeK[tau,h,:] ----------------
// thread = (tau, head): timeK segment held in REGISTERS; Q broadcast from smem.
#define QTROWS 32
__global__ void __launch_bounds__(256) k_qt(const float* __restrict__ timeK) {
    __shared__ __align__(16) float sQ[QTROWS*128];   // 16 KB
    int t = threadIdx.x;
    int w = t >> 5, lane = t & 31;
    int h = w & 3;
    int tau = blockIdx.y*64 + (w >> 2)*32 + lane;
    int r0 = blockIdx.x * QTROWS;
    bool valid = (tau < NTAU);

    float4 tr[8];
    if (valid) {
        const float4* src = (const float4*)&timeK[tau*128 + h*32];
        #pragma unroll
        for (int j = 0; j < 8; ++j) tr[j] = src[j];
    }

    { // stage 32 Q rows (coalesced)
        const float4* src = (const float4*)&g_Q[r0*128];
        float4* dst = (float4*)sQ;
        #pragma unroll
        for (int j = 0; j < 4; ++j) dst[t + 256*j] = src[t + 256*j];
    }
    __syncthreads();
    if (valid) {
        for (int r = 0; r < QTROWS; ++r) {
            const float4* qp = (const float4*)&sQ[r*128 + h*32]; // broadcast
            float a = 0.f;
            #pragma unroll
            for (int j = 0; j < 8; ++j) {
                float4 q4 = qp[j];
                a += tr[j].x*q4.x + tr[j].y*q4.y + tr[j].z*q4.z + tr[j].w*q4.w;
            }
            g_dqt[((size_t)(r0 + r)*NTAU + tau)*4 + h] = a;
        }
    }
}

// ---------------- K2: tiled attention (TQ2 queries/block, smem-staged K/V) ----------------
__global__ void __launch_bounds__(256) k_attn(const int* __restrict__ log_seqs,
                                              const int* __restrict__ time_mat) {
    extern __shared__ __align__(16) char smem_raw[];
    float* sKV = (float*)smem_raw;                 // CH*PADK = 8448
    float* sQ  = sKV + 8448;                       // TQ2*128 = 512
    float* sS  = sQ  + 512;                        // TQ2*4*256 = 4096
    int*   s_tm  = (int*)(sS + 4096);              // TQ2*256 = 1024
    int*   s_pad = s_tm + 1024;                    // 4

    int t = threadIdx.x;                           // 256
    int b  = blockIdx.x >> 6;
    int q0 = (blockIdx.x & 63) * TQ2;
    int row0 = b*Lc + q0;
    int brow = b*Lc;

    { // Q tile: 512 floats = 128 float4
        if (t < 128) {
            const float4* src = (const float4*)&g_Q[row0*128];
            ((float4*)sQ)[t] = src[t];
        }
    }
    { // tm tile: 1024 ints = 256 int4
        const int4* src = (const int4*)&time_mat[row0*256];
        ((int4*)s_tm)[t] = src[t];
    }
    if (t < TQ2) s_pad[t] = (log_seqs[row0 + t] == 0);
    { // init sS = NEGV
        float4 negv = make_float4(NEGV, NEGV, NEGV, NEGV);
        float4* p = (float4*)sS;
        #pragma unroll
        for (int i = 0; i < 4; ++i) p[t + 256*i] = negv;
    }
    __syncthreads();

    int nkt = ((q0 + TQ2 - 1) >> 6) + 1;

    // ---- pass 1: scores ----
    int q = t >> 6, kl = t & 63;
    for (int kt = 0; kt < nkt; ++kt) {
        int k0 = kt * CH;
        { // coalesced load Kc chunk: 2048 float4
            const float4* src = (const float4*)&g_Kc[(brow + k0)*128];
            float4* dst = (float4*)sKV;
            #pragma unroll
            for (int j = 0; j < 8; ++j) {
                int f4 = t + 256*j;
                dst[(f4 >> 5)*33 + (f4 & 31)] = src[f4];
            }
        }
        __syncthreads();
        int kg = k0 + kl;
        if (!s_pad[q] && kg <= q0 + q) {
            const float4* kr = (const float4*)&sKV[kl*PADK];
            const float4* qr = (const float4*)&sQ[q*128];   // broadcast
            float sc[4] = {0.f, 0.f, 0.f, 0.f};
            #pragma unroll
            for (int j = 0; j < 32; ++j) {
                float4 kv = kr[j], qv = qr[j];
                sc[j >> 3] += kv.x*qv.x + kv.y*qv.y + kv.z*qv.z + kv.w*qv.w;
            }
            int tau = s_tm[q*256 + kg];
            float4 dq = *(const float4*)&g_dqt[((size_t)(row0 + q)*NTAU + tau)*4];
            sS[(q*4+0)*256 + kg] = (sc[0] + dq.x) * SCALE;
            sS[(q*4+1)*256 + kg] = (sc[1] + dq.y) * SCALE;
            sS[(q*4+2)*256 + kg] = (sc[2] + dq.z) * SCALE;
            sS[(q*4+3)*256 + kg] = (sc[3] + dq.w) * SCALE;
        }
        __syncthreads();
    }

    // ---- pass 2: softmax (16 rows of 256; each warp handles 2 rows) ----
    {
        int w = t >> 5, lane = t & 31;
        #pragma unroll
        for (int j = 0; j < 2; ++j) {
            float* p = sS + (w + j*8)*256;
            float x[8];
            float mx = -3.4e38f;
            #pragma unroll
            for (int i = 0; i < 8; ++i) { x[i] = p[lane + 32*i]; mx = fmaxf(mx, x[i]); }
            #pragma unroll
            for (int o = 16; o >= 1; o >>= 1)
                mx = fmaxf(mx, __shfl_xor_sync(0xffffffffu, mx, o));
            float s = 0.f;
            #pragma unroll
            for (int i = 0; i < 8; ++i) { x[i] = expf(x[i] - mx); s += x[i]; }
            #pragma unroll
            for (int o = 16; o >= 1; o >>= 1)
                s += __shfl_xor_sync(0xffffffffu, s, o);
            float inv = 1.f / s;
            #pragma unroll
            for (int i = 0; i < 8; ++i) p[lane + 32*i] = x[i] * inv;
        }
    }
    __syncthreads();

    // ---- pass 3: out = A @ (Vc + timeV[bf16]) ----
    int col = t & 127, qp = t >> 7;     // q in {qp, qp+2}
    int h = col >> 5;
    float acc0 = 0.f, acc1 = 0.f;
    for (int kt = 0; kt < nkt; ++kt) {
        int k0 = kt * CH;
        __syncthreads();
        { // coalesced load Vc chunk
            const float4* src = (const float4*)&g_Vc[(brow + k0)*128];
            float4* dst = (float4*)sKV;
            #pragma unroll
            for (int j = 0; j < 8; ++j) {
                int f4 = t + 256*j;
                dst[(f4 >> 5)*33 + (f4 & 31)] = src[f4];
            }
        }
        __syncthreads();
        for (int k = 0; k < CH; ++k) {
            int kg = k0 + k;
            float v = sKV[k*PADK + col];
            float a0 = sS[(qp*4 + h)*256 + kg];          // broadcast
            if (a0 != 0.f) {                              // uniform branch per warp
                float tv = __bfloat162float(g_tVb[s_tm[qp*256 + kg]*128 + col]);
                acc0 = fmaf(a0, v + tv, acc0);
            }
            float a1 = sS[((qp+2)*4 + h)*256 + kg];
            if (a1 != 0.f) {
                float tv = __bfloat162float(g_tVb[s_tm[(qp+2)*256 + kg]*128 + col]);
                acc1 = fmaf(a1, v + tv, acc1);
            }
        }
    }
    {
        int i0 = (row0 + qp)*128 + col;
        int i1 = (row0 + qp + 2)*128 + col;
        g_seqs[i0] = g_qin[i0] + acc0;
        g_seqs[i1] = g_qin[i1] + acc1;
    }
}

// ---------------- K3: LN2 + FFN + residual + pad-mask (+ LN1 of next layer) ----------------
__global__ void __launch_bounds__(128) k_ffn(const int* __restrict__ log_seqs,
                      const float* __restrict__ ln2_g, const float* __restrict__ ln2_b,
                      const float* __restrict__ W1, const float* __restrict__ b1,
                      const float* __restrict__ W2, const float* __restrict__ b2,
                      const float* __restrict__ ng, const float* __restrict__ nb) {
    __shared__ __align__(16) float s_y[RF][Dc];
    __shared__ __align__(16) float s_h[RF][Dc];
    __shared__ float s_mean[RF], s_inv[RF];
    __shared__ int   s_pad[RF];
    int t = threadIdx.x;
    int row0 = blockIdx.x * RF;
    int r = t >> 5, lane = t & 31;

    for (int i = t; i < RF*Dc; i += 128)
        ((float*)s_h)[i] = g_seqs[row0*Dc + i];
    if (t < RF) s_pad[t] = (log_seqs[row0 + t] == 0);
    __syncthreads();

    {
        float4 v4 = *(const float4*)&s_h[r][lane*4];
        float s  = v4.x + v4.y + v4.z + v4.w;
        float ss = v4.x*v4.x + v4.y*v4.y + v4.z*v4.z + v4.w*v4.w;
        #pragma unroll
        for (int o = 16; o >= 1; o >>= 1) {
            s  += __shfl_xor_sync(0xffffffffu, s,  o);
            ss += __shfl_xor_sync(0xffffffffu, ss, o);
        }
        if (lane == 0) {
            float m = s * (1.f/Dc);
            float var = ss * (1.f/Dc) - m*m;
            s_mean[r] = m;
            s_inv[r]  = rsqrtf(var + 1e-8f);
        }
    }
    __syncthreads();

    float g = ln2_g[t], bb = ln2_b[t];
    #pragma unroll
    for (int rr = 0; rr < RF; ++rr)
        s_y[rr][t] = (s_h[rr][t] - s_mean[rr]) * s_inv[rr] * g + bb;
    __syncthreads();

    float a1[RF];
    #pragma unroll
    for (int rr = 0; rr < RF; ++rr) a1[rr] = 0.f;
    for (int k = 0; k < Dc; k += 4) {
        float w0=W1[(k+0)*Dc+t], w1=W1[(k+1)*Dc+t], w2=W1[(k+2)*Dc+t], w3=W1[(k+3)*Dc+t];
        #pragma unroll
        for (int rr = 0; rr < RF; ++rr) {
            float4 y = *(const float4*)&s_y[rr][k];
            a1[rr] = fmaf(y.x,w0, fmaf(y.y,w1, fmaf(y.z,w2, fmaf(y.w,w3, a1[rr]))));
        }
    }
    float b1v = b1[t];
    __syncthreads();
    #pragma unroll
    for (int rr = 0; rr < RF; ++rr)
        s_h[rr][t] = fmaxf(a1[rr] + b1v, 0.f);
    __syncthreads();

    float a2[RF];
    #pragma unroll
    for (int rr = 0; rr < RF; ++rr) a2[rr] = 0.f;
    for (int k = 0; k < Dc; k += 4) {
        float w0=W2[(k+0)*Dc+t], w1=W2[(k+1)*Dc+t], w2=W2[(k+2)*Dc+t], w3=W2[(k+3)*Dc+t];
        #pragma unroll
        for (int rr = 0; rr < RF; ++rr) {
            float4 h4 = *(const float4*)&s_h[rr][k];
            a2[rr] = fmaf(h4.x,w0, fmaf(h4.y,w1, fmaf(h4.z,w2, fmaf(h4.w,w3, a2[rr]))));
        }
    }
    float b2v = b2[t];
    float vout[RF];
    #pragma unroll
    for (int rr = 0; rr < RF; ++rr) {
        vout[rr] = s_pad[rr] ? 0.f : (s_y[rr][t] + a2[rr] + b2v);
        g_seqs[(row0 + rr)*Dc + t] = vout[rr];
    }

    if (ng) {  // LN1 of next layer, fused
        __syncthreads();
        #pragma unroll
        for (int rr = 0; rr < RF; ++rr) s_h[rr][t] = vout[rr];
        __syncthreads();
        {
            float4 v4 = *(const float4*)&s_h[r][lane*4];
            float s  = v4.x + v4.y + v4.z + v4.w;
            float ss = v4.x*v4.x + v4.y*v4.y + v4.z*v4.z + v4.w*v4.w;
            #pragma unroll
            for (int o = 16; o >= 1; o >>= 1) {
                s  += __shfl_xor_sync(0xffffffffu, s,  o);
                ss += __shfl_xor_sync(0xffffffffu, ss, o);
            }
            if (lane == 0) {
                float m = s * (1.f/Dc);
                float var = ss * (1.f/Dc) - m*m;
                s_mean[r] = m;
                s_inv[r]  = rsqrtf(var + 1e-8f);
            }
        }
        __syncthreads();
        float gg = ng[t], bb2 = nb[t];
        #pragma unroll
        for (int rr = 0; rr < RF; ++rr)
            g_qin[(row0 + rr)*Dc + t] = (s_h[rr][t] - s_mean[rr]) * s_inv[rr] * gg + bb2;
    }
}

// ---------------- K4: final LN + pos/neg logits ----------------
__global__ void __launch_bounds__(128) k_logits(
                         const int* __restrict__ pos_seqs, const int* __restrict__ neg_seqs,
                         const float* __restrict__ item_emb,
                         const float* __restrict__ lnf_g, const float* __restrict__ lnf_b,
                         float* __restrict__ out) {
    __shared__ float r1[4], r2[4];
    int row = blockIdx.x, t = threadIdx.x;
    int warp = t >> 5, lane = t & 31;

    float x = g_seqs[row*Dc + t];
    float s = x, ss = x*x;
    #pragma unroll
    for (int o = 16; o >= 1; o >>= 1) {
        s  += __shfl_xor_sync(0xffffffffu, s,  o);
        ss += __shfl_xor_sync(0xffffffffu, ss, o);
    }
    if (lane == 0) { r1[warp] = s; r2[warp] = ss; }
    __syncthreads();
    float tot  = r1[0]+r1[1]+r1[2]+r1[3];
    float tots = r2[0]+r2[1]+r2[2]+r2[3];
    float m = tot * (1.f/Dc);
    float inv = rsqrtf(tots * (1.f/Dc) - m*m + 1e-8f);
    float f = (x - m) * inv * lnf_g[t] + lnf_b[t];

    int pi = pos_seqs[row], ni = neg_seqs[row];
    float pp = f * item_emb[pi*Dc + t];
    float nn = f * item_emb[ni*Dc + t];
    #pragma unroll
    for (int o = 16; o >= 1; o >>= 1) {
        pp += __shfl_xor_sync(0xffffffffu, pp, o);
        nn += __shfl_xor_sync(0xffffffffu, nn, o);
    }
    __syncthreads();
    if (lane == 0) { r1[warp] = pp; r2[warp] = nn; }
    __syncthreads();
    if (t == 0) {
        out[row]        = r1[0]+r1[1]+r1[2]+r1[3];
        out[NROW + row] = r2[0]+r2[1]+r2[2]+r2[3];
    }
}

// ---------------- launch ----------------
extern "C" void kernel_launch(void* const* d_in, const int* in_sizes, int n_in,
                              void* d_out, int out_size) {
    const int*   log_seqs = (const int*)  d_in[1];
    const int*   time_mat = (const int*)  d_in[2];
    const int*   pos_seqs = (const int*)  d_in[3];
    const int*   neg_seqs = (const int*)  d_in[4];
    const float* item_emb = (const float*)d_in[5];
    const float* posK     = (const float*)d_in[6];
    const float* posV     = (const float*)d_in[7];
    const float* timeK    = (const float*)d_in[8];
    const float* timeV    = (const float*)d_in[9];
    const float* ln1_g    = (const float*)d_in[10];
    const float* ln1_b    = (const float*)d_in[11];
    const float* Wq       = (const float*)d_in[12];
    const float* bq       = (const float*)d_in[13];
    const float* Wk       = (const float*)d_in[14];
    const float* bk       = (const float*)d_in[15];
    const float* Wv       = (const float*)d_in[16];
    const float* bv       = (const float*)d_in[17];
    const float* ln2_g    = (const float*)d_in[18];
    const float* ln2_b    = (const float*)d_in[19];
    const float* W1       = (const float*)d_in[20];
    const float* b1       = (const float*)d_in[21];
    const float* W2       = (const float*)d_in[22];
    const float* b2       = (const float*)d_in[23];
    const float* lnf_g    = (const float*)d_in[24];
    const float* lnf_b    = (const float*)d_in[25];
    float* out = (float*)d_out;

    cudaFuncSetAttribute(k_attn, cudaFuncAttributeMaxDynamicSharedMemorySize, SMEM_ATTN);

    k_cvt<<<(NTAU*Dc + 255)/256, 256>>>(timeV);
    k_embed<<<NROW, 128>>>(log_seqs, item_emb, ln1_g, ln1_b);
    for (int i = 0; i < 2; ++i) {
        dim3 gq(NROW/RQ, 3);
        k_qkv<<<gq, 128>>>(Wq + i*Dc*Dc, Wk + i*Dc*Dc, Wv + i*Dc*Dc,
                           bq + i*Dc, bk + i*Dc, bv + i*Dc, posK, posV);
        dim3 gt(NROW/QTROWS, 5);          // (64, 5) = 320 blocks
        k_qt<<<gt, 256>>>(timeK);
        k_attn<<<NROW/TQ2, 256, SMEM_ATTN>>>(log_seqs, time_mat);
        const float* ng = (i == 0) ? (ln1_g + Dc) : nullptr;
        const float* nb = (i == 0) ? (ln1_b + Dc) : nullptr;
        k_ffn<<<NROW/RF, 128>>>(log_seqs, ln2_g + i*Dc, ln2_b + i*Dc,
                                W1 + i*Dc*Dc, b1 + i*Dc,
                                W2 + i*Dc*Dc, b2 + i*Dc, ng, nb);
    }
    k_logits<<<NROW, 128>>>(pos_seqs, neg_seqs, item_emb, lnf_g, lnf_b, out);
}